// round 15
// baseline (speedup 1.0000x reference)
#include <cuda_runtime.h>
#include <cuda_fp16.h>
#include <cstdint>

// ---------------------------------------------------------------------------
// DeformRoIPooling (deformable PS-RoI pooling), GROUP_SIZE=1 specialization.
//
// data:   (B=2, C=256, H=128, W=128) f32
// rois:   (N=128, 5) f32  [b, x1, y1, x2, y2]
// offset: (N=128, 2, 7, 7) f32
// out:    (N=128, 256, 7, 7) f32
//
// R15: R14 with __launch_bounds__(224, 7): 40 regs x 224 thr x 7 blocks =
//      62720 regs < 64K -> 49 resident warps/SM (vs 42), single wave.
//      Kernel is latency-exposed (issue 40%, L1 45%); occupancy converts
//      directly into speed (R14 evidence).
// ---------------------------------------------------------------------------

#define BQ   2
#define CQ   256
#define HQ   128
#define WQ   128
#define NROI 128
#define PQ   7
#define SQ   4
#define SPATIAL_SCALE 0.0625f
#define TRANS_STD 0.1f

// 16 MB transposed fp16 scratch: (B, H, W, C) — L2-resident
__device__ __half g_tdata[(size_t)BQ * HQ * WQ * CQ];

// ---------------------------------------------------------------------------
// Transpose + f32->fp16 convert: per batch, (C=256) x (P=16384) -> (P) x (C).
// (~7.4us, at its 48MB compulsory-DRAM floor — leave alone.)
// ---------------------------------------------------------------------------
__global__ void __launch_bounds__(256) transpose_kernel(const float* __restrict__ src) {
    __shared__ float tile[32][68];
    const int b  = blockIdx.z;
    const int c0 = blockIdx.y * 32;
    const int p0 = blockIdx.x * 64;
    const float* s = src + ((size_t)b * CQ + c0) * (HQ * WQ) + p0;
    __half* d      = g_tdata + (size_t)b * HQ * WQ * CQ;

    const int i = threadIdx.x;
    {
        const int c = i >> 4;
        const int q = i & 15;
        #pragma unroll
        for (int r = 0; r < 2; r++) {
            float4 v = *(const float4*)(s + (size_t)(c + 16 * r) * (HQ * WQ) + 4 * q);
            *(float4*)&tile[c + 16 * r][4 * q] = v;
        }
    }
    __syncthreads();
    {
        const int p = i >> 2;               // 0..63
        const int q = i & 3;                // 0..3 -> channel group of 8
        __half2 h[4];
        #pragma unroll
        for (int k = 0; k < 4; k++) {
            float2 f;
            f.x = tile[q * 8 + 2 * k + 0][p];
            f.y = tile[q * 8 + 2 * k + 1][p];
            h[k] = __float22half2_rn(f);
        }
        *(uint4*)(d + (size_t)(p0 + p) * CQ + c0 + 8 * q) = *(const uint4*)h;
    }
}

// ---------------------------------------------------------------------------
// Packed f32x2 helpers
// ---------------------------------------------------------------------------
__device__ __forceinline__ void add2(unsigned long long& d, unsigned long long a) {
    asm("add.rn.f32x2 %0, %0, %1;" : "+l"(d) : "l"(a));
}
__device__ __forceinline__ unsigned long long f2_to_u64(float2 f) {
    unsigned long long r;
    asm("mov.b64 %0, {%1, %2};" : "=l"(r) : "f"(f.x), "f"(f.y));
    return r;
}
__device__ __forceinline__ void unpack2(unsigned long long v, float& lo, float& hi) {
    asm("mov.b64 {%0, %1}, %2;" : "=f"(lo), "=f"(hi) : "l"(v));
}

// Per-sample record in shared memory (32B: int4 offsets + 4 duplicated half2 weights)
struct __align__(16) SampleRec {
    int4    o;                     // element offsets of the 4 corners
    __half2 w00, w01, w10, w11;    // duplicated fp16 bilinear weights
};

// ---------------------------------------------------------------------------
// Pool: block = (32, 7): blockIdx.x = ph, threadIdx.y = pw. One warp per bin.
// Thread t -> channels 8t..8t+7. Results staged in SMEM, written coalesced.
// ---------------------------------------------------------------------------
__global__ void __launch_bounds__(224, 7) pool_kernel(
    const float* __restrict__ rois,
    const float* __restrict__ offset,
    float* __restrict__ out)
{
    __shared__ __align__(16) float st[PQ][260];   // [pw][channel], padded row
    __shared__ SampleRec stab[PQ][16];
    __shared__ float scount[8];

    const int pw = threadIdx.y;            // 0..6
    const int ph = blockIdx.x;             // 0..6
    const int n  = blockIdx.y;             // 0..127
    const int t  = threadIdx.x;            // 0..31

    const int bidx = (int)__ldg(&rois[n * 5 + 0]); // batch (uniform)

    // ---- per-bin table build: 16 lanes, one per sample (warp-private) ----
    if (t < 16) {
        const int s  = t;
        const int ih = s >> 2;
        const int iw = s & 3;

        // geometry (replicates reference IEEE f32 ops)
        const float* r = rois + n * 5;
        const float rsw = rintf(__ldg(&r[1])) * SPATIAL_SCALE - 0.5f;
        const float rsh = rintf(__ldg(&r[2])) * SPATIAL_SCALE - 0.5f;
        const float rew = (rintf(__ldg(&r[3])) + 1.0f) * SPATIAL_SCALE - 0.5f;
        const float reh = (rintf(__ldg(&r[4])) + 1.0f) * SPATIAL_SCALE - 0.5f;
        const float rw = fmaxf(rew - rsw, 0.1f);
        const float rh = fmaxf(reh - rsh, 0.1f);
        const float binw = rw / (float)PQ;
        const float binh = rh / (float)PQ;
        const float subw = binw / (float)SQ;
        const float subh = binh / (float)SQ;

        const int part_h = (int)floorf((float)ph / (float)PQ * (float)PQ);
        const int part_w = (int)floorf((float)pw / (float)PQ * (float)PQ);

        const float tx_off = __ldg(&offset[n * (2 * PQ * PQ) + part_h * PQ + part_w]) * TRANS_STD;
        const float ty_off = __ldg(&offset[n * (2 * PQ * PQ) + PQ * PQ + part_h * PQ + part_w]) * TRANS_STD;

        const float wstart = (float)pw * binw + rsw + tx_off * rw;
        const float hstart = (float)ph * binh + rsh + ty_off * rh;

        const float h  = hstart + (float)ih * subh;
        const float w  = wstart + (float)iw * subw;
        const bool  vh = (h >= -0.5f) && (h <= (float)HQ - 0.5f);
        const bool  vw = (w >= -0.5f) && (w <= (float)WQ - 0.5f);
        const bool  valid = vh && vw;

        const float hc  = fminf(fmaxf(h, 0.f), (float)(HQ - 1));
        const float wc  = fminf(fmaxf(w, 0.f), (float)(WQ - 1));
        const float y0f = floorf(hc);
        const float x0f = floorf(wc);
        const float dy  = hc - y0f;
        const float dx  = wc - x0f;
        const int y0 = (int)y0f;
        const int x0 = (int)x0f;
        const int y1 = min(y0 + 1, HQ - 1);
        const int x1 = min(x0 + 1, WQ - 1);

        const float w00 = valid ? (1.f - dy) * (1.f - dx) : 0.f;
        const float w01 = valid ? (1.f - dy) * dx         : 0.f;
        const float w10 = valid ? dy * (1.f - dx)         : 0.f;
        const float w11 = valid ? dy * dx                 : 0.f;

        SampleRec rec;
        rec.o = make_int4(y0 * (WQ * CQ) + x0 * CQ,
                          y0 * (WQ * CQ) + x1 * CQ,
                          y1 * (WQ * CQ) + x0 * CQ,
                          y1 * (WQ * CQ) + x1 * CQ);
        rec.w00 = __float2half2_rn(w00);
        rec.w01 = __float2half2_rn(w01);
        rec.w10 = __float2half2_rn(w10);
        rec.w11 = __float2half2_rn(w11);
        stab[pw][s] = rec;

        if (s == 0) {
            float nvh = 0.f, nvw = 0.f;
            #pragma unroll
            for (int k = 0; k < SQ; k++) {
                const float hh = hstart + (float)k * subh;
                const float ww = wstart + (float)k * subw;
                nvh += ((hh >= -0.5f) && (hh <= (float)HQ - 0.5f)) ? 1.f : 0.f;
                nvw += ((ww >= -0.5f) && (ww <= (float)WQ - 0.5f)) ? 1.f : 0.f;
            }
            scount[pw] = nvh * nvw;
        }
    }
    __syncwarp();   // table is warp-private

    // ---- hot loop: 16 samples; HFMA2 corner interp, f32x2 accumulation ----
    const __half* base = g_tdata + (size_t)bidx * HQ * WQ * CQ + 8 * t;

    unsigned long long acc0 = 0ull, acc1 = 0ull, acc2 = 0ull, acc3 = 0ull;

    #pragma unroll
    for (int s = 0; s < 16; s++) {
        const SampleRec rec = stab[pw][s];

        const uint4 u00 = __ldg((const uint4*)(base + rec.o.x));
        const uint4 u01 = __ldg((const uint4*)(base + rec.o.y));
        const uint4 u10 = __ldg((const uint4*)(base + rec.o.z));
        const uint4 u11 = __ldg((const uint4*)(base + rec.o.w));

        const __half2* h00 = (const __half2*)&u00;
        const __half2* h01 = (const __half2*)&u01;
        const __half2* h10 = (const __half2*)&u10;
        const __half2* h11 = (const __half2*)&u11;

        __half2 s0 = __hmul2(rec.w00, h00[0]);
        __half2 s1 = __hmul2(rec.w00, h00[1]);
        __half2 s2 = __hmul2(rec.w00, h00[2]);
        __half2 s3 = __hmul2(rec.w00, h00[3]);
        s0 = __hfma2(rec.w01, h01[0], s0);
        s1 = __hfma2(rec.w01, h01[1], s1);
        s2 = __hfma2(rec.w01, h01[2], s2);
        s3 = __hfma2(rec.w01, h01[3], s3);
        s0 = __hfma2(rec.w10, h10[0], s0);
        s1 = __hfma2(rec.w10, h10[1], s1);
        s2 = __hfma2(rec.w10, h10[2], s2);
        s3 = __hfma2(rec.w10, h10[3], s3);
        s0 = __hfma2(rec.w11, h11[0], s0);
        s1 = __hfma2(rec.w11, h11[1], s1);
        s2 = __hfma2(rec.w11, h11[2], s2);
        s3 = __hfma2(rec.w11, h11[3], s3);

        add2(acc0, f2_to_u64(__half22float2(s0)));
        add2(acc1, f2_to_u64(__half22float2(s1)));
        add2(acc2, f2_to_u64(__half22float2(s2)));
        add2(acc3, f2_to_u64(__half22float2(s3)));
    }

    // ---- epilogue: one reciprocal, 8 multiplies, stage into SMEM ----
    const float count = scount[pw];
    const float inv = (count > 0.f) ? (1.0f / count) : 0.f;

    float a[8];
    unpack2(acc0, a[0], a[1]);
    unpack2(acc1, a[2], a[3]);
    unpack2(acc2, a[4], a[5]);
    unpack2(acc3, a[6], a[7]);

    float4 lo = make_float4(a[0] * inv, a[1] * inv, a[2] * inv, a[3] * inv);
    float4 hi = make_float4(a[4] * inv, a[5] * inv, a[6] * inv, a[7] * inv);
    *(float4*)&st[pw][8 * t]     = lo;
    *(float4*)&st[pw][8 * t + 4] = hi;

    __syncthreads();

    // ---- coalesced write-out: 1792 values = 256 channels x 7 pw ----
    const int tid = pw * 32 + t;          // 0..223
    float* obase = out + (size_t)n * (CQ * PQ * PQ) + ph * PQ;
    #pragma unroll
    for (int i = 0; i < 8; i++) {
        const int f = tid + i * 224;      // 0..1791
        const int c  = f / PQ;
        const int p2 = f - c * PQ;
        obase[c * (PQ * PQ) + p2] = st[p2][c];
    }
}

extern "C" void kernel_launch(void* const* d_in, const int* in_sizes, int n_in,
                              void* d_out, int out_size) {
    const float* data   = (const float*)d_in[0];
    const float* rois   = (const float*)d_in[1];
    const float* offset = (const float*)d_in[2];
    float* out = (float*)d_out;

    dim3 tg(HQ * WQ / 64, CQ / 32, BQ);     // (256, 8, 2)
    transpose_kernel<<<tg, 256>>>(data);

    dim3 pg(PQ, NROI);                      // (ph, n)
    dim3 pb(32, PQ);
    pool_kernel<<<pg, pb>>>(rois, offset, out);
}

// round 16
// speedup vs baseline: 1.0106x; 1.0106x over previous
#include <cuda_runtime.h>
#include <cuda_fp16.h>
#include <cstdint>

// ---------------------------------------------------------------------------
// DeformRoIPooling (deformable PS-RoI pooling), GROUP_SIZE=1 specialization.
//
// data:   (B=2, C=256, H=128, W=128) f32
// rois:   (N=128, 5) f32  [b, x1, y1, x2, y2]
// offset: (N=128, 2, 7, 7) f32
// out:    (N=128, 256, 7, 7) f32
//
// R16: R14 per-warp work (fp16 scratch, 1 warp/bin, 64x flat LDG.128, HFMA2
//      interp, f32x2 accumulate, staged coalesced stores) repartitioned into
//      4-warp blocks over GLOBAL bin index -> grid 1568, 12 blocks/SM,
//      single balanced wave (R14's 896-block/6-per-SM config left an 8-block
//      second wave that doubled pool time).
// ---------------------------------------------------------------------------

#define BQ   2
#define CQ   256
#define HQ   128
#define WQ   128
#define NROI 128
#define PQ   7
#define SQ   4
#define SPATIAL_SCALE 0.0625f
#define TRANS_STD 0.1f

// 16 MB transposed fp16 scratch: (B, H, W, C) — L2-resident
__device__ __half g_tdata[(size_t)BQ * HQ * WQ * CQ];

// ---------------------------------------------------------------------------
// Transpose + f32->fp16 convert: per batch, (C=256) x (P=16384) -> (P) x (C).
// ---------------------------------------------------------------------------
__global__ void __launch_bounds__(256) transpose_kernel(const float* __restrict__ src) {
    __shared__ float tile[32][68];
    const int b  = blockIdx.z;
    const int c0 = blockIdx.y * 32;
    const int p0 = blockIdx.x * 64;
    const float* s = src + ((size_t)b * CQ + c0) * (HQ * WQ) + p0;
    __half* d      = g_tdata + (size_t)b * HQ * WQ * CQ;

    const int i = threadIdx.x;
    {
        const int c = i >> 4;
        const int q = i & 15;
        #pragma unroll
        for (int r = 0; r < 2; r++) {
            float4 v = *(const float4*)(s + (size_t)(c + 16 * r) * (HQ * WQ) + 4 * q);
            *(float4*)&tile[c + 16 * r][4 * q] = v;
        }
    }
    __syncthreads();
    {
        const int p = i >> 2;               // 0..63
        const int q = i & 3;                // 0..3 -> channel group of 8
        __half2 h[4];
        #pragma unroll
        for (int k = 0; k < 4; k++) {
            float2 f;
            f.x = tile[q * 8 + 2 * k + 0][p];
            f.y = tile[q * 8 + 2 * k + 1][p];
            h[k] = __float22half2_rn(f);
        }
        *(uint4*)(d + (size_t)(p0 + p) * CQ + c0 + 8 * q) = *(const uint4*)h;
    }
}

// ---------------------------------------------------------------------------
// Packed f32x2 helpers
// ---------------------------------------------------------------------------
__device__ __forceinline__ void add2(unsigned long long& d, unsigned long long a) {
    asm("add.rn.f32x2 %0, %0, %1;" : "+l"(d) : "l"(a));
}
__device__ __forceinline__ unsigned long long f2_to_u64(float2 f) {
    unsigned long long r;
    asm("mov.b64 %0, {%1, %2};" : "=l"(r) : "f"(f.x), "f"(f.y));
    return r;
}
__device__ __forceinline__ void unpack2(unsigned long long v, float& lo, float& hi) {
    asm("mov.b64 {%0, %1}, %2;" : "=f"(lo), "=f"(hi) : "l"(v));
}

// Per-sample record in shared memory (32B: int4 offsets + 4 duplicated half2 weights)
struct __align__(16) SampleRec {
    int4    o;                     // element offsets of the 4 corners
    __half2 w00, w01, w10, w11;    // duplicated fp16 bilinear weights
};

// ---------------------------------------------------------------------------
// Pool: block = (32, 4) = 4 warps, warp w -> GLOBAL bin g = blockIdx.x*4 + w.
// roi n = g/49, bin-in-roi = g%49. Thread t -> channels 8t..8t+7.
// ---------------------------------------------------------------------------
__global__ void __launch_bounds__(128, 12) pool_kernel(
    const float* __restrict__ rois,
    const float* __restrict__ offset,
    float* __restrict__ out)
{
    __shared__ __align__(16) float st[4][260];   // [slot][channel] staging
    __shared__ SampleRec stab[4][16];
    __shared__ float scount[4];

    const int slot = threadIdx.y;                 // 0..3
    const int g    = blockIdx.x * 4 + slot;       // global bin, 0..6271
    const int n    = g / 49;                      // roi
    const int lb   = g - n * 49;                  // bin in roi
    const int ph   = lb / PQ;
    const int pw   = lb - ph * PQ;
    const int t    = threadIdx.x;                 // 0..31

    const int bidx = (int)__ldg(&rois[n * 5 + 0]); // batch (uniform per warp)

    // ---- per-bin table build: 16 lanes, one per sample (warp-private) ----
    if (t < 16) {
        const int s  = t;
        const int ih = s >> 2;
        const int iw = s & 3;

        // geometry (replicates reference IEEE f32 ops)
        const float* r = rois + n * 5;
        const float rsw = rintf(__ldg(&r[1])) * SPATIAL_SCALE - 0.5f;
        const float rsh = rintf(__ldg(&r[2])) * SPATIAL_SCALE - 0.5f;
        const float rew = (rintf(__ldg(&r[3])) + 1.0f) * SPATIAL_SCALE - 0.5f;
        const float reh = (rintf(__ldg(&r[4])) + 1.0f) * SPATIAL_SCALE - 0.5f;
        const float rw = fmaxf(rew - rsw, 0.1f);
        const float rh = fmaxf(reh - rsh, 0.1f);
        const float binw = rw / (float)PQ;
        const float binh = rh / (float)PQ;
        const float subw = binw / (float)SQ;
        const float subh = binh / (float)SQ;

        const int part_h = (int)floorf((float)ph / (float)PQ * (float)PQ);
        const int part_w = (int)floorf((float)pw / (float)PQ * (float)PQ);

        const float tx_off = __ldg(&offset[n * (2 * PQ * PQ) + part_h * PQ + part_w]) * TRANS_STD;
        const float ty_off = __ldg(&offset[n * (2 * PQ * PQ) + PQ * PQ + part_h * PQ + part_w]) * TRANS_STD;

        const float wstart = (float)pw * binw + rsw + tx_off * rw;
        const float hstart = (float)ph * binh + rsh + ty_off * rh;

        const float h  = hstart + (float)ih * subh;
        const float w  = wstart + (float)iw * subw;
        const bool  vh = (h >= -0.5f) && (h <= (float)HQ - 0.5f);
        const bool  vw = (w >= -0.5f) && (w <= (float)WQ - 0.5f);
        const bool  valid = vh && vw;

        const float hc  = fminf(fmaxf(h, 0.f), (float)(HQ - 1));
        const float wc  = fminf(fmaxf(w, 0.f), (float)(WQ - 1));
        const float y0f = floorf(hc);
        const float x0f = floorf(wc);
        const float dy  = hc - y0f;
        const float dx  = wc - x0f;
        const int y0 = (int)y0f;
        const int x0 = (int)x0f;
        const int y1 = min(y0 + 1, HQ - 1);
        const int x1 = min(x0 + 1, WQ - 1);

        const float w00 = valid ? (1.f - dy) * (1.f - dx) : 0.f;
        const float w01 = valid ? (1.f - dy) * dx         : 0.f;
        const float w10 = valid ? dy * (1.f - dx)         : 0.f;
        const float w11 = valid ? dy * dx                 : 0.f;

        SampleRec rec;
        rec.o = make_int4(y0 * (WQ * CQ) + x0 * CQ,
                          y0 * (WQ * CQ) + x1 * CQ,
                          y1 * (WQ * CQ) + x0 * CQ,
                          y1 * (WQ * CQ) + x1 * CQ);
        rec.w00 = __float2half2_rn(w00);
        rec.w01 = __float2half2_rn(w01);
        rec.w10 = __float2half2_rn(w10);
        rec.w11 = __float2half2_rn(w11);
        stab[slot][s] = rec;

        if (s == 0) {
            float nvh = 0.f, nvw = 0.f;
            #pragma unroll
            for (int k = 0; k < SQ; k++) {
                const float hh = hstart + (float)k * subh;
                const float ww = wstart + (float)k * subw;
                nvh += ((hh >= -0.5f) && (hh <= (float)HQ - 0.5f)) ? 1.f : 0.f;
                nvw += ((ww >= -0.5f) && (ww <= (float)WQ - 0.5f)) ? 1.f : 0.f;
            }
            scount[slot] = nvh * nvw;
        }
    }
    __syncwarp();   // table is warp-private

    // ---- hot loop: 16 samples; HFMA2 corner interp, f32x2 accumulation ----
    const __half* base = g_tdata + (size_t)bidx * HQ * WQ * CQ + 8 * t;

    unsigned long long acc0 = 0ull, acc1 = 0ull, acc2 = 0ull, acc3 = 0ull;

    #pragma unroll
    for (int s = 0; s < 16; s++) {
        const SampleRec rec = stab[slot][s];

        const uint4 u00 = __ldg((const uint4*)(base + rec.o.x));
        const uint4 u01 = __ldg((const uint4*)(base + rec.o.y));
        const uint4 u10 = __ldg((const uint4*)(base + rec.o.z));
        const uint4 u11 = __ldg((const uint4*)(base + rec.o.w));

        const __half2* h00 = (const __half2*)&u00;
        const __half2* h01 = (const __half2*)&u01;
        const __half2* h10 = (const __half2*)&u10;
        const __half2* h11 = (const __half2*)&u11;

        __half2 s0 = __hmul2(rec.w00, h00[0]);
        __half2 s1 = __hmul2(rec.w00, h00[1]);
        __half2 s2 = __hmul2(rec.w00, h00[2]);
        __half2 s3 = __hmul2(rec.w00, h00[3]);
        s0 = __hfma2(rec.w01, h01[0], s0);
        s1 = __hfma2(rec.w01, h01[1], s1);
        s2 = __hfma2(rec.w01, h01[2], s2);
        s3 = __hfma2(rec.w01, h01[3], s3);
        s0 = __hfma2(rec.w10, h10[0], s0);
        s1 = __hfma2(rec.w10, h10[1], s1);
        s2 = __hfma2(rec.w10, h10[2], s2);
        s3 = __hfma2(rec.w10, h10[3], s3);
        s0 = __hfma2(rec.w11, h11[0], s0);
        s1 = __hfma2(rec.w11, h11[1], s1);
        s2 = __hfma2(rec.w11, h11[2], s2);
        s3 = __hfma2(rec.w11, h11[3], s3);

        add2(acc0, f2_to_u64(__half22float2(s0)));
        add2(acc1, f2_to_u64(__half22float2(s1)));
        add2(acc2, f2_to_u64(__half22float2(s2)));
        add2(acc3, f2_to_u64(__half22float2(s3)));
    }

    // ---- epilogue: one reciprocal, 8 multiplies, stage into SMEM ----
    const float count = scount[slot];
    const float inv = (count > 0.f) ? (1.0f / count) : 0.f;

    float a[8];
    unpack2(acc0, a[0], a[1]);
    unpack2(acc1, a[2], a[3]);
    unpack2(acc2, a[4], a[5]);
    unpack2(acc3, a[6], a[7]);

    float4 lo = make_float4(a[0] * inv, a[1] * inv, a[2] * inv, a[3] * inv);
    float4 hi = make_float4(a[4] * inv, a[5] * inv, a[6] * inv, a[7] * inv);
    *(float4*)&st[slot][8 * t]     = lo;
    *(float4*)&st[slot][8 * t + 4] = hi;

    __syncthreads();

    // ---- coalesced write-out: 1024 values = 256 channels x 4 global bins ----
    // f ordered (c major, slot minor): runs of 4 consecutive bins are 16B
    // contiguous in out when they don't cross a roi boundary.
    const int tid = slot * 32 + t;         // 0..127
    const int g0  = blockIdx.x * 4;
    #pragma unroll
    for (int i = 0; i < 8; i++) {
        const int f  = tid + i * 128;      // 0..1023
        const int c  = f >> 2;             // 0..255
        const int sl = f & 3;              // bin slot
        const int gg = g0 + sl;
        const int nn = gg / 49;
        const int bb = gg - nn * 49;
        out[(size_t)nn * (CQ * 49) + c * 49 + bb] = st[sl][c];
    }
}

extern "C" void kernel_launch(void* const* d_in, const int* in_sizes, int n_in,
                              void* d_out, int out_size) {
    const float* data   = (const float*)d_in[0];
    const float* rois   = (const float*)d_in[1];
    const float* offset = (const float*)d_in[2];
    float* out = (float*)d_out;

    dim3 tg(HQ * WQ / 64, CQ / 32, BQ);     // (256, 8, 2)
    transpose_kernel<<<tg, 256>>>(data);

    dim3 pg(NROI * PQ * PQ / 4, 1);         // 1568 blocks x 4 bins
    dim3 pb(32, 4);
    pool_kernel<<<pg, pb>>>(rois, offset, out);
}